// round 1
// baseline (speedup 1.0000x reference)
#include <cuda_runtime.h>
#include <math.h>
#include <stdint.h>

// ---------------------------------------------------------------------------
// Problem constants (fixed by the reference)
// ---------------------------------------------------------------------------
#define BATCH   4
#define NBOX    30
#define IN_DIM  768
#define POS_DIM 64
#define HDIM    832            // IN_DIM + POS_DIM
#define H1DIM   512
#define H2DIM   512
#define OUT_DIM 768
#define ROWS    (BATCH * NBOX) // 120

#define HW64  4096
#define DIM64 4126             // HW64 + NBOX
#define HW32  1024
#define DIM32 1054

// Output layout: [objs | sim64 | sim32] flattened f32
#define OFF_OBJ  ((size_t)0)
#define OFF_S64  ((size_t)ROWS * OUT_DIM)                              // 92160
#define OFF_S32  (OFF_S64 + (size_t)BATCH * DIM64 * DIM64)             // +68095504

// ---------------------------------------------------------------------------
// Scratch (static device globals; no allocation at runtime)
// ---------------------------------------------------------------------------
__device__ float    g_h [ROWS * HDIM];
__device__ float    g_a1[ROWS * H1DIM];
__device__ float    g_a2[ROWS * H2DIM];
__device__ unsigned g_bits64[BATCH * HW64];
__device__ unsigned g_bits32[BATCH * HW32];

// ---------------------------------------------------------------------------
// Rasterize boxes into per-pixel 32-bit membership masks.
// bit n (n<29): pixel inside box n AND masks[b,n]==1
// bit 29: covered by no valid box (the "null" slot)
// ---------------------------------------------------------------------------
__global__ void bits_kernel(const float* __restrict__ boxes,
                            const float* __restrict__ masks,
                            int size)
{
    int b = blockIdx.y;
    __shared__ int      s_x1[NBOX], s_y1[NBOX], s_x2[NBOX], s_y2[NBOX];
    __shared__ unsigned s_valid;

    int t = threadIdx.x;
    if (t == 0) s_valid = 0u;
    __syncthreads();
    if (t < NBOX) {
        const float* bb = boxes + ((size_t)b * NBOX + t) * 4;
        // boxes*size is exact (size is a power of 2); rintf = round half-to-even,
        // matching jnp.round.
        s_x1[t] = (int)rintf(bb[0] * (float)size);
        s_y1[t] = (int)rintf(bb[1] * (float)size);
        s_x2[t] = (int)rintf(bb[2] * (float)size);
        s_y2[t] = (int)rintf(bb[3] * (float)size);
        if (t < NBOX - 1 && masks[b * NBOX + t] == 1.0f)
            atomicOr(&s_valid, 1u << t);
    }
    __syncthreads();
    unsigned vm = s_valid;
    int HW = size * size;
    unsigned* bits = (size == 64) ? g_bits64 : g_bits32;

    for (int p = blockIdx.x * blockDim.x + t; p < HW; p += gridDim.x * blockDim.x) {
        int y = p / size, x = p - y * size;
        unsigned m = 0u;
#pragma unroll
        for (int n = 0; n < NBOX - 1; n++) {
            bool in = (y >= s_y1[n]) & (y < s_y2[n]) & (x >= s_x1[n]) & (x < s_x2[n]);
            if (in) m |= (1u << n);
        }
        m &= vm;
        if (m == 0u) m = (1u << (NBOX - 1));   // null slot
        bits[b * HW + p] = m;
    }
}

// ---------------------------------------------------------------------------
// Build MLP input h[row, 0:832] = [pe_masked | fourier_masked]
// ---------------------------------------------------------------------------
__global__ void prep_h_kernel(const float* __restrict__ boxes,
                              const float* __restrict__ masks,
                              const float* __restrict__ pembed,
                              const float* __restrict__ pos_table,
                              const float* __restrict__ null_positive,
                              const float* __restrict__ null_position)
{
    int row = blockIdx.x;          // 0..119
    int b = row / NBOX, n = row - b * NBOX;
    float m  = masks[b * NBOX + n];
    float om = 1.0f - m;

    for (int k = threadIdx.x; k < IN_DIM; k += blockDim.x) {
        float v = pembed[(size_t)row * IN_DIM + k] + pos_table[(size_t)n * IN_DIM + k];
        g_h[(size_t)row * HDIM + k] = v * m + om * null_positive[k];
    }
    if (threadIdx.x < POS_DIM) {
        int k = threadIdx.x;
        int fi = k >> 3;           // frequency index 0..7
        int c8 = k & 7;            // 0-3: sin of coord, 4-7: cos of coord
        int coord = c8 & 3;
        float freq = powf(100.0f, (float)fi * 0.125f);
        float arg  = boxes[((size_t)row) * 4 + coord] * freq;
        float e    = (c8 < 4) ? sinf(arg) : cosf(arg);
        g_h[(size_t)row * HDIM + IN_DIM + k] = e * m + om * null_position[k];
    }
}

// ---------------------------------------------------------------------------
// MLP layer: out[120,NOUT] = act( A[120,K] @ W[K,NOUT] + bias )
// Tiling: 8 rows x 64 cols per block, 256 threads, each thread 2 outputs.
// LAYER selects static scratch buffers (device symbols not addressable on host).
// ---------------------------------------------------------------------------
template<int K, int NOUT, bool SILU, int LAYER>
__global__ void __launch_bounds__(256)
mlp_layer(const float* __restrict__ W, const float* __restrict__ bias,
          float* __restrict__ extout)
{
    __shared__ float sA[8][K];
    const float* A = (LAYER == 1) ? g_h : ((LAYER == 2) ? g_a1 : g_a2);
    float* out     = (LAYER == 3) ? extout : ((LAYER == 1) ? g_a1 : g_a2);

    int row0    = blockIdx.y * 8;
    int colBase = blockIdx.x * 64;
    int t = threadIdx.x;

    for (int idx = t; idx < 8 * K; idx += 256) {
        int r = idx / K, k = idx - r * K;
        sA[r][k] = A[(size_t)(row0 + r) * K + k];
    }
    __syncthreads();

    int j  = t & 63;
    int rp = t >> 6;            // 0..3
    int r0 = rp * 2;

    float acc0 = 0.f, acc1 = 0.f;
    const float* Wp = W + colBase + j;
#pragma unroll 8
    for (int k = 0; k < K; k++) {
        float w = __ldg(Wp + (size_t)k * NOUT);
        acc0 = fmaf(w, sA[r0][k],     acc0);
        acc1 = fmaf(w, sA[r0 + 1][k], acc1);
    }
    float bj = bias[colBase + j];
    acc0 += bj; acc1 += bj;
    if (SILU) {
        acc0 = acc0 / (1.0f + expf(-acc0));
        acc1 = acc1 / (1.0f + expf(-acc1));
    }
    out[(size_t)(row0 + r0)     * NOUT + colBase + j] = acc0;
    out[(size_t)(row0 + r0 + 1) * NOUT + colBase + j] = acc1;
}

// ---------------------------------------------------------------------------
// sim fill: full[b] is DIM x DIM where DIM = HW + 30.
//   rows p <  HW: cols q < HW  -> (bits[p] & bits[q]) != 0
//                 cols q >= HW -> (bits[p] >> (q-HW)) & 1
//   rows p >= HW: zeros
// One block = 32 rows of one batch; full bits table staged in smem.
// ---------------------------------------------------------------------------
__global__ void __launch_bounds__(256)
sim_fill(float* __restrict__ outBase, int HW, int DIM)
{
    __shared__ unsigned sbits[HW64];   // max 16 KB
    int b = blockIdx.y;
    const unsigned* bits = ((HW == HW64) ? g_bits64 : g_bits32) + (size_t)b * HW;
    for (int i = threadIdx.x; i < HW; i += 256) sbits[i] = bits[i];
    __syncthreads();

    const uint2* sb2 = (const uint2*)sbits;
    int half = DIM >> 1;       // DIM is even
    int HW2  = HW >> 1;
    size_t bbase = (size_t)b * DIM * DIM;

    for (int pi = 0; pi < 32; pi++) {
        int p = blockIdx.x * 32 + pi;
        if (p >= DIM) break;
        float2* rowp = (float2*)(outBase + bbase + (size_t)p * DIM); // 8B aligned: p*DIM even
        if (p >= HW) {
            float2 z = make_float2(0.f, 0.f);
            for (int i = threadIdx.x; i < half; i += 256) rowp[i] = z;
        } else {
            unsigned rb = sbits[p];
            for (int i = threadIdx.x; i < half; i += 256) {
                float2 v;
                if (i < HW2) {
                    uint2 s = sb2[i];
                    v.x = (rb & s.x) ? 1.f : 0.f;
                    v.y = (rb & s.y) ? 1.f : 0.f;
                } else {
                    int n = i * 2 - HW;          // 0..28, even
                    v.x = ((rb >> n)       & 1u) ? 1.f : 0.f;
                    v.y = ((rb >> (n + 1)) & 1u) ? 1.f : 0.f;
                }
                rowp[i] = v;
            }
        }
    }
}

// ---------------------------------------------------------------------------
// Launch
// ---------------------------------------------------------------------------
extern "C" void kernel_launch(void* const* d_in, const int* in_sizes, int n_in,
                              void* d_out, int out_size)
{
    const float* boxes      = (const float*)d_in[0];
    const float* masks      = (const float*)d_in[1];
    const float* pembed     = (const float*)d_in[2];
    const float* pos_table  = (const float*)d_in[3];
    const float* W1         = (const float*)d_in[4];
    const float* b1         = (const float*)d_in[5];
    const float* W2         = (const float*)d_in[6];
    const float* b2         = (const float*)d_in[7];
    const float* W3         = (const float*)d_in[8];
    const float* b3         = (const float*)d_in[9];
    const float* null_pos   = (const float*)d_in[10];
    const float* null_xyxy  = (const float*)d_in[11];
    float* out = (float*)d_out;

    // membership bitmasks
    bits_kernel<<<dim3(8, BATCH), 256>>>(boxes, masks, 64);
    bits_kernel<<<dim3(2, BATCH), 256>>>(boxes, masks, 32);

    // MLP input
    prep_h_kernel<<<ROWS, 256>>>(boxes, masks, pembed, pos_table, null_pos, null_xyxy);

    // MLP layers (8x64 tiles)
    mlp_layer<HDIM,  H1DIM,  true,  1><<<dim3(H1DIM  / 64, ROWS / 8), 256>>>(W1, b1, nullptr);
    mlp_layer<H1DIM, H2DIM,  true,  2><<<dim3(H2DIM  / 64, ROWS / 8), 256>>>(W2, b2, nullptr);
    mlp_layer<H2DIM, OUT_DIM, false, 3><<<dim3(OUT_DIM / 64, ROWS / 8), 256>>>(W3, b3, out + OFF_OBJ);

    // similarity masks (bulk of the DRAM traffic)
    sim_fill<<<dim3((DIM64 + 31) / 32, BATCH), 256>>>(out + OFF_S64, HW64, DIM64);
    sim_fill<<<dim3((DIM32 + 31) / 32, BATCH), 256>>>(out + OFF_S32, HW32, DIM32);
}

// round 2
// speedup vs baseline: 1.3889x; 1.3889x over previous
#include <cuda_runtime.h>
#include <math.h>
#include <stdint.h>

// ---------------------------------------------------------------------------
// Problem constants (fixed by the reference)
// ---------------------------------------------------------------------------
#define BATCH   4
#define NBOX    30
#define IN_DIM  768
#define POS_DIM 64
#define HDIM    832            // IN_DIM + POS_DIM
#define H1DIM   512
#define H2DIM   512
#define OUT_DIM 768
#define ROWS    (BATCH * NBOX) // 120

#define HW64  4096
#define DIM64 4126             // HW64 + NBOX
#define HW32  1024
#define DIM32 1054

// Output layout: [objs | sim64 | sim32] flattened f32
#define OFF_OBJ  ((size_t)0)
#define OFF_S64  ((size_t)ROWS * OUT_DIM)                              // 92160
#define OFF_S32  (OFF_S64 + (size_t)BATCH * DIM64 * DIM64)             // +68095504

// ---------------------------------------------------------------------------
// Scratch (static device globals; no allocation at runtime)
// ---------------------------------------------------------------------------
__device__ float    g_h [ROWS * HDIM];
__device__ float    g_a1[ROWS * H1DIM];
__device__ float    g_a2[ROWS * H2DIM];
__device__ unsigned g_bits64[BATCH * HW64];
__device__ unsigned g_bits32[BATCH * HW32];

// ---------------------------------------------------------------------------
// Rasterize boxes into per-pixel 32-bit membership masks.
// bit n (n<29): pixel inside box n AND masks[b,n]==1
// bit 29: covered by no valid box (the "null" slot)
// ---------------------------------------------------------------------------
__global__ void bits_kernel(const float* __restrict__ boxes,
                            const float* __restrict__ masks,
                            int size)
{
    int b = blockIdx.y;
    __shared__ int      s_x1[NBOX], s_y1[NBOX], s_x2[NBOX], s_y2[NBOX];
    __shared__ unsigned s_valid;

    int t = threadIdx.x;
    if (t == 0) s_valid = 0u;
    __syncthreads();
    if (t < NBOX) {
        const float* bb = boxes + ((size_t)b * NBOX + t) * 4;
        // boxes*size is exact (size is a power of 2); rintf = round half-to-even,
        // matching jnp.round.
        s_x1[t] = (int)rintf(bb[0] * (float)size);
        s_y1[t] = (int)rintf(bb[1] * (float)size);
        s_x2[t] = (int)rintf(bb[2] * (float)size);
        s_y2[t] = (int)rintf(bb[3] * (float)size);
        if (t < NBOX - 1 && masks[b * NBOX + t] == 1.0f)
            atomicOr(&s_valid, 1u << t);
    }
    __syncthreads();
    unsigned vm = s_valid;
    int HW = size * size;
    unsigned* bits = (size == 64) ? g_bits64 : g_bits32;

    for (int p = blockIdx.x * blockDim.x + t; p < HW; p += gridDim.x * blockDim.x) {
        int y = p / size, x = p - y * size;
        unsigned m = 0u;
#pragma unroll
        for (int n = 0; n < NBOX - 1; n++) {
            bool in = (y >= s_y1[n]) & (y < s_y2[n]) & (x >= s_x1[n]) & (x < s_x2[n]);
            if (in) m |= (1u << n);
        }
        m &= vm;
        if (m == 0u) m = (1u << (NBOX - 1));   // null slot
        bits[b * HW + p] = m;
    }
}

// ---------------------------------------------------------------------------
// Build MLP input h[row, 0:832] = [pe_masked | fourier_masked]
// ---------------------------------------------------------------------------
__global__ void prep_h_kernel(const float* __restrict__ boxes,
                              const float* __restrict__ masks,
                              const float* __restrict__ pembed,
                              const float* __restrict__ pos_table,
                              const float* __restrict__ null_positive,
                              const float* __restrict__ null_position)
{
    int row = blockIdx.x;          // 0..119
    int b = row / NBOX, n = row - b * NBOX;
    float m  = masks[b * NBOX + n];
    float om = 1.0f - m;

    for (int k = threadIdx.x; k < IN_DIM; k += blockDim.x) {
        float v = pembed[(size_t)row * IN_DIM + k] + pos_table[(size_t)n * IN_DIM + k];
        g_h[(size_t)row * HDIM + k] = v * m + om * null_positive[k];
    }
    if (threadIdx.x < POS_DIM) {
        int k = threadIdx.x;
        int fi = k >> 3;           // frequency index 0..7
        int c8 = k & 7;            // 0-3: sin of coord, 4-7: cos of coord
        int coord = c8 & 3;
        float freq = powf(100.0f, (float)fi * 0.125f);
        float arg  = boxes[((size_t)row) * 4 + coord] * freq;
        float e    = (c8 < 4) ? sinf(arg) : cosf(arg);
        g_h[(size_t)row * HDIM + IN_DIM + k] = e * m + om * null_position[k];
    }
}

// ---------------------------------------------------------------------------
// MLP layer: out[120,NOUT] = act( A[120,K] @ W[K,NOUT] + bias )
//
// Block = 8 rows x 64 cols, 256 threads = 64 cols x 4 K-slices.
// Each thread: 8 row-accumulators over its K/4 slice (8-way ILP, W reused
// across 8 rows from a register). A tile staged in smem, read as float4
// (warp-uniform address -> broadcast, conflict-free). Cross-slice smem
// reduction, then bias + SiLU + store.
// ---------------------------------------------------------------------------
template<int K, int NOUT, bool SILU, int LAYER>
__global__ void __launch_bounds__(256)
mlp_layer(const float* __restrict__ W, const float* __restrict__ bias,
          float* __restrict__ extout)
{
    constexpr int L  = K / 4;     // floats per K-slice (208 or 128)
    constexpr int L4 = L / 4;     // float4 steps per slice (52 or 32)

    __shared__ float4 sA[8][K / 4];          // 8 rows x K floats
    __shared__ float  sRed[4][8][65];        // [slice][row][col] (+1 pad)

    const float* A = (LAYER == 1) ? g_h : ((LAYER == 2) ? g_a1 : g_a2);
    float* out     = (LAYER == 3) ? extout : ((LAYER == 1) ? g_a1 : g_a2);

    int row0    = blockIdx.y * 8;
    int colBase = blockIdx.x * 64;
    int t  = threadIdx.x;
    int j  = t & 63;              // column within tile
    int ks = t >> 6;              // K-slice 0..3

    // stage A tile (coalesced: consecutive t -> consecutive k)
    {
        float* sAf = (float*)sA;
        for (int idx = t; idx < 8 * K; idx += 256) {
            int r = idx / K, k = idx - r * K;
            sAf[r * K + k] = A[(size_t)(row0 + r) * K + k];
        }
    }
    __syncthreads();

    float acc[8];
#pragma unroll
    for (int r = 0; r < 8; r++) acc[r] = 0.f;

    const float* Wp = W + (size_t)(ks * L) * NOUT + colBase + j;
    const int a4base = ks * L4;

#pragma unroll 2
    for (int i4 = 0; i4 < L4; i4++) {
        float w0 = __ldg(Wp + (size_t)(i4 * 4 + 0) * NOUT);
        float w1 = __ldg(Wp + (size_t)(i4 * 4 + 1) * NOUT);
        float w2 = __ldg(Wp + (size_t)(i4 * 4 + 2) * NOUT);
        float w3 = __ldg(Wp + (size_t)(i4 * 4 + 3) * NOUT);
#pragma unroll
        for (int r = 0; r < 8; r++) {
            float4 a = sA[r][a4base + i4];
            acc[r] = fmaf(w0, a.x, acc[r]);
            acc[r] = fmaf(w1, a.y, acc[r]);
            acc[r] = fmaf(w2, a.z, acc[r]);
            acc[r] = fmaf(w3, a.w, acc[r]);
        }
    }

#pragma unroll
    for (int r = 0; r < 8; r++) sRed[ks][r][j] = acc[r];
    __syncthreads();

    // finalize: thread (j, ks) handles rows 2*ks, 2*ks+1
    float bj = bias[colBase + j];
#pragma unroll
    for (int rr = 0; rr < 2; rr++) {
        int r = ks * 2 + rr;
        float v = sRed[0][r][j] + sRed[1][r][j] + sRed[2][r][j] + sRed[3][r][j] + bj;
        if (SILU) v = v / (1.0f + expf(-v));
        out[(size_t)(row0 + r) * NOUT + colBase + j] = v;
    }
}

// ---------------------------------------------------------------------------
// sim fill: full[b] is DIM x DIM where DIM = HW + 30.
//   rows p <  HW: cols q < HW  -> (bits[p] & bits[q]) != 0
//                 cols q >= HW -> (bits[p] >> (q-HW)) & 1
//   rows p >= HW: zeros
// One block = 32 rows of one batch; full bits table staged in smem.
// ---------------------------------------------------------------------------
__global__ void __launch_bounds__(256)
sim_fill(float* __restrict__ outBase, int HW, int DIM)
{
    __shared__ unsigned sbits[HW64];   // max 16 KB
    int b = blockIdx.y;
    const unsigned* bits = ((HW == HW64) ? g_bits64 : g_bits32) + (size_t)b * HW;
    for (int i = threadIdx.x; i < HW; i += 256) sbits[i] = bits[i];
    __syncthreads();

    const uint2* sb2 = (const uint2*)sbits;
    int half = DIM >> 1;       // DIM is even
    int HW2  = HW >> 1;
    size_t bbase = (size_t)b * DIM * DIM;

    for (int pi = 0; pi < 32; pi++) {
        int p = blockIdx.x * 32 + pi;
        if (p >= DIM) break;
        float2* rowp = (float2*)(outBase + bbase + (size_t)p * DIM); // 8B aligned: p*DIM even
        if (p >= HW) {
            float2 z = make_float2(0.f, 0.f);
            for (int i = threadIdx.x; i < half; i += 256) rowp[i] = z;
        } else {
            unsigned rb = sbits[p];
            for (int i = threadIdx.x; i < half; i += 256) {
                float2 v;
                if (i < HW2) {
                    uint2 s = sb2[i];
                    v.x = (rb & s.x) ? 1.f : 0.f;
                    v.y = (rb & s.y) ? 1.f : 0.f;
                } else {
                    int n = i * 2 - HW;          // 0..28, even
                    v.x = ((rb >> n)       & 1u) ? 1.f : 0.f;
                    v.y = ((rb >> (n + 1)) & 1u) ? 1.f : 0.f;
                }
                rowp[i] = v;
            }
        }
    }
}

// ---------------------------------------------------------------------------
// Launch
// ---------------------------------------------------------------------------
extern "C" void kernel_launch(void* const* d_in, const int* in_sizes, int n_in,
                              void* d_out, int out_size)
{
    const float* boxes      = (const float*)d_in[0];
    const float* masks      = (const float*)d_in[1];
    const float* pembed     = (const float*)d_in[2];
    const float* pos_table  = (const float*)d_in[3];
    const float* W1         = (const float*)d_in[4];
    const float* b1         = (const float*)d_in[5];
    const float* W2         = (const float*)d_in[6];
    const float* b2         = (const float*)d_in[7];
    const float* W3         = (const float*)d_in[8];
    const float* b3         = (const float*)d_in[9];
    const float* null_pos   = (const float*)d_in[10];
    const float* null_xyxy  = (const float*)d_in[11];
    float* out = (float*)d_out;

    // membership bitmasks
    bits_kernel<<<dim3(8, BATCH), 256>>>(boxes, masks, 64);
    bits_kernel<<<dim3(2, BATCH), 256>>>(boxes, masks, 32);

    // MLP input
    prep_h_kernel<<<ROWS, 256>>>(boxes, masks, pembed, pos_table, null_pos, null_xyxy);

    // MLP layers (8 rows x 64 cols tiles, 4-way split-K inside the block)
    mlp_layer<HDIM,  H1DIM,  true,  1><<<dim3(H1DIM  / 64, ROWS / 8), 256>>>(W1, b1, nullptr);
    mlp_layer<H1DIM, H2DIM,  true,  2><<<dim3(H2DIM  / 64, ROWS / 8), 256>>>(W2, b2, nullptr);
    mlp_layer<H2DIM, OUT_DIM, false, 3><<<dim3(OUT_DIM / 64, ROWS / 8), 256>>>(W3, b3, out + OFF_OBJ);

    // similarity masks (bulk of the DRAM traffic)
    sim_fill<<<dim3((DIM64 + 31) / 32, BATCH), 256>>>(out + OFF_S64, HW64, DIM64);
    sim_fill<<<dim3((DIM32 + 31) / 32, BATCH), 256>>>(out + OFF_S32, HW32, DIM32);
}

// round 3
// speedup vs baseline: 1.7756x; 1.2784x over previous
#include <cuda_runtime.h>
#include <math.h>
#include <stdint.h>

// ---------------------------------------------------------------------------
// Problem constants (fixed by the reference)
// ---------------------------------------------------------------------------
#define BATCH   4
#define NBOX    30
#define IN_DIM  768
#define POS_DIM 64
#define HDIM    832            // IN_DIM + POS_DIM
#define H1DIM   512
#define H2DIM   512
#define OUT_DIM 768
#define ROWS    (BATCH * NBOX) // 120

#define HW64  4096
#define DIM64 4126             // HW64 + NBOX
#define HW32  1024
#define DIM32 1054

// Output layout: [objs | sim64 | sim32] flattened f32
#define OFF_OBJ  ((size_t)0)
#define OFF_S64  ((size_t)ROWS * OUT_DIM)                              // 92160
#define OFF_S32  (OFF_S64 + (size_t)BATCH * DIM64 * DIM64)             // +68095504

// ---------------------------------------------------------------------------
// Scratch (static device globals; no allocation at runtime)
// ---------------------------------------------------------------------------
__device__ float    g_h [ROWS * HDIM];
__device__ float    g_a1[ROWS * H1DIM];
__device__ float    g_a2[ROWS * H2DIM];
__device__ unsigned g_bits64[BATCH * HW64];
__device__ unsigned g_bits32[BATCH * HW32];

// ---------------------------------------------------------------------------
// Rasterize boxes into per-pixel 32-bit membership masks.
// bit n (n<29): pixel inside box n AND masks[b,n]==1
// bit 29: covered by no valid box (the "null" slot)
// ---------------------------------------------------------------------------
__global__ void bits_kernel(const float* __restrict__ boxes,
                            const float* __restrict__ masks,
                            int size)
{
    int b = blockIdx.y;
    __shared__ int      s_x1[NBOX], s_y1[NBOX], s_x2[NBOX], s_y2[NBOX];
    __shared__ unsigned s_valid;

    int t = threadIdx.x;
    if (t == 0) s_valid = 0u;
    __syncthreads();
    if (t < NBOX) {
        const float* bb = boxes + ((size_t)b * NBOX + t) * 4;
        // boxes*size is exact (size is a power of 2); rintf = round half-to-even,
        // matching jnp.round.
        s_x1[t] = (int)rintf(bb[0] * (float)size);
        s_y1[t] = (int)rintf(bb[1] * (float)size);
        s_x2[t] = (int)rintf(bb[2] * (float)size);
        s_y2[t] = (int)rintf(bb[3] * (float)size);
        if (t < NBOX - 1 && masks[b * NBOX + t] == 1.0f)
            atomicOr(&s_valid, 1u << t);
    }
    __syncthreads();
    unsigned vm = s_valid;
    int HW = size * size;
    unsigned* bits = (size == 64) ? g_bits64 : g_bits32;

    for (int p = blockIdx.x * blockDim.x + t; p < HW; p += gridDim.x * blockDim.x) {
        int y = p / size, x = p - y * size;
        unsigned m = 0u;
#pragma unroll
        for (int n = 0; n < NBOX - 1; n++) {
            bool in = (y >= s_y1[n]) & (y < s_y2[n]) & (x >= s_x1[n]) & (x < s_x2[n]);
            if (in) m |= (1u << n);
        }
        m &= vm;
        if (m == 0u) m = (1u << (NBOX - 1));   // null slot
        bits[b * HW + p] = m;
    }
}

// ---------------------------------------------------------------------------
// Build MLP input h[row, 0:832] = [pe_masked | fourier_masked]
// ---------------------------------------------------------------------------
__global__ void prep_h_kernel(const float* __restrict__ boxes,
                              const float* __restrict__ masks,
                              const float* __restrict__ pembed,
                              const float* __restrict__ pos_table,
                              const float* __restrict__ null_positive,
                              const float* __restrict__ null_position)
{
    int row = blockIdx.x;          // 0..119
    int b = row / NBOX, n = row - b * NBOX;
    float m  = masks[b * NBOX + n];
    float om = 1.0f - m;

    for (int k = threadIdx.x; k < IN_DIM; k += blockDim.x) {
        float v = pembed[(size_t)row * IN_DIM + k] + pos_table[(size_t)n * IN_DIM + k];
        g_h[(size_t)row * HDIM + k] = v * m + om * null_positive[k];
    }
    if (threadIdx.x < POS_DIM) {
        int k = threadIdx.x;
        int fi = k >> 3;           // frequency index 0..7
        int c8 = k & 7;            // 0-3: sin of coord, 4-7: cos of coord
        int coord = c8 & 3;
        float freq = powf(100.0f, (float)fi * 0.125f);
        float arg  = boxes[((size_t)row) * 4 + coord] * freq;
        float e    = (c8 < 4) ? sinf(arg) : cosf(arg);
        g_h[(size_t)row * HDIM + IN_DIM + k] = e * m + om * null_position[k];
    }
}

// ---------------------------------------------------------------------------
// MLP layer: out[120,NOUT] = act( A[120,K] @ W[K,NOUT] + bias )
//
// Block = 8 rows x 64 cols, 512 threads = 64 cols x 8 K-slices (16 warps/SM
// for latency hiding). Each thread: 8 row-accumulators over its K/8 slice,
// with double-buffered register prefetch of the next 4 W values so the L2
// latency overlaps the 32 FMAs of the current group. A tile in smem, read
// as float4 broadcast. Cross-slice smem reduction (slice ks -> row ks),
// then bias + SiLU + store.
// ---------------------------------------------------------------------------
template<int K, int NOUT, bool SILU, int LAYER>
__global__ void __launch_bounds__(512)
mlp_layer(const float* __restrict__ W, const float* __restrict__ bias,
          float* __restrict__ extout)
{
    constexpr int NS = 8;         // K-slices per block
    constexpr int L  = K / NS;    // floats per K-slice (104 or 64)
    constexpr int L4 = L / 4;     // float4 steps per slice (26 or 16)

    __shared__ float4 sA[8][K / 4];          // 8 rows x K floats
    __shared__ float  sRed[NS][8][65];       // [slice][row][col] (+1 pad)

    const float* A = (LAYER == 1) ? g_h : ((LAYER == 2) ? g_a1 : g_a2);
    float* out     = (LAYER == 3) ? extout : ((LAYER == 1) ? g_a1 : g_a2);

    int row0    = blockIdx.y * 8;
    int colBase = blockIdx.x * 64;
    int t  = threadIdx.x;
    int j  = t & 63;              // column within tile
    int ks = t >> 6;              // K-slice 0..7

    // stage A tile (coalesced)
    {
        float* sAf = (float*)sA;
        for (int idx = t; idx < 8 * K; idx += 512) {
            int r = idx / K, k = idx - r * K;
            sAf[r * K + k] = A[(size_t)(row0 + r) * K + k];
        }
    }
    __syncthreads();

    float acc[8];
#pragma unroll
    for (int r = 0; r < 8; r++) acc[r] = 0.f;

    const float* Wp = W + (size_t)(ks * L) * NOUT + colBase + j;
    const int a4base = ks * L4;

    // double-buffered W prefetch
    float w0 = __ldg(Wp + (size_t)0 * NOUT);
    float w1 = __ldg(Wp + (size_t)1 * NOUT);
    float w2 = __ldg(Wp + (size_t)2 * NOUT);
    float w3 = __ldg(Wp + (size_t)3 * NOUT);

#pragma unroll
    for (int i4 = 0; i4 < L4; i4++) {
        float n0, n1, n2, n3;
        if (i4 + 1 < L4) {
            const float* Wn = Wp + (size_t)((i4 + 1) * 4) * NOUT;
            n0 = __ldg(Wn + (size_t)0 * NOUT);
            n1 = __ldg(Wn + (size_t)1 * NOUT);
            n2 = __ldg(Wn + (size_t)2 * NOUT);
            n3 = __ldg(Wn + (size_t)3 * NOUT);
        }
#pragma unroll
        for (int r = 0; r < 8; r++) {
            float4 a = sA[r][a4base + i4];
            acc[r] = fmaf(w0, a.x, acc[r]);
            acc[r] = fmaf(w1, a.y, acc[r]);
            acc[r] = fmaf(w2, a.z, acc[r]);
            acc[r] = fmaf(w3, a.w, acc[r]);
        }
        if (i4 + 1 < L4) { w0 = n0; w1 = n1; w2 = n2; w3 = n3; }
    }

#pragma unroll
    for (int r = 0; r < 8; r++) sRed[ks][r][j] = acc[r];
    __syncthreads();

    // finalize: thread (j, ks) handles row ks
    {
        int r = ks;
        float v = bias[colBase + j];
#pragma unroll
        for (int s = 0; s < NS; s++) v += sRed[s][r][j];
        if (SILU) v = v / (1.0f + expf(-v));
        out[(size_t)(row0 + r) * NOUT + colBase + j] = v;
    }
}

// ---------------------------------------------------------------------------
// sim fill: full[b] is DIM x DIM where DIM = HW + 30.
//   rows p <  HW: cols q < HW  -> (bits[p] & bits[q]) != 0
//                 cols q >= HW -> (bits[p] >> (q-HW)) & 1
//   rows p >= HW: zeros
// One block = 32 rows of one batch; full bits table staged in smem.
// ---------------------------------------------------------------------------
__global__ void __launch_bounds__(256)
sim_fill(float* __restrict__ outBase, int HW, int DIM)
{
    __shared__ unsigned sbits[HW64];   // max 16 KB
    int b = blockIdx.y;
    const unsigned* bits = ((HW == HW64) ? g_bits64 : g_bits32) + (size_t)b * HW;
    for (int i = threadIdx.x; i < HW; i += 256) sbits[i] = bits[i];
    __syncthreads();

    const uint2* sb2 = (const uint2*)sbits;
    int half = DIM >> 1;       // DIM is even
    int HW2  = HW >> 1;
    size_t bbase = (size_t)b * DIM * DIM;

    for (int pi = 0; pi < 32; pi++) {
        int p = blockIdx.x * 32 + pi;
        if (p >= DIM) break;
        float2* rowp = (float2*)(outBase + bbase + (size_t)p * DIM); // 8B aligned: p*DIM even
        if (p >= HW) {
            float2 z = make_float2(0.f, 0.f);
            for (int i = threadIdx.x; i < half; i += 256) rowp[i] = z;
        } else {
            unsigned rb = sbits[p];
            for (int i = threadIdx.x; i < half; i += 256) {
                float2 v;
                if (i < HW2) {
                    uint2 s = sb2[i];
                    v.x = (rb & s.x) ? 1.f : 0.f;
                    v.y = (rb & s.y) ? 1.f : 0.f;
                } else {
                    int n = i * 2 - HW;          // 0..28, even
                    v.x = ((rb >> n)       & 1u) ? 1.f : 0.f;
                    v.y = ((rb >> (n + 1)) & 1u) ? 1.f : 0.f;
                }
                rowp[i] = v;
            }
        }
    }
}

// ---------------------------------------------------------------------------
// Launch
// ---------------------------------------------------------------------------
extern "C" void kernel_launch(void* const* d_in, const int* in_sizes, int n_in,
                              void* d_out, int out_size)
{
    const float* boxes      = (const float*)d_in[0];
    const float* masks      = (const float*)d_in[1];
    const float* pembed     = (const float*)d_in[2];
    const float* pos_table  = (const float*)d_in[3];
    const float* W1         = (const float*)d_in[4];
    const float* b1         = (const float*)d_in[5];
    const float* W2         = (const float*)d_in[6];
    const float* b2         = (const float*)d_in[7];
    const float* W3         = (const float*)d_in[8];
    const float* b3         = (const float*)d_in[9];
    const float* null_pos   = (const float*)d_in[10];
    const float* null_xyxy  = (const float*)d_in[11];
    float* out = (float*)d_out;

    // membership bitmasks
    bits_kernel<<<dim3(8, BATCH), 256>>>(boxes, masks, 64);
    bits_kernel<<<dim3(2, BATCH), 256>>>(boxes, masks, 32);

    // MLP input
    prep_h_kernel<<<ROWS, 256>>>(boxes, masks, pembed, pos_table, null_pos, null_xyxy);

    // MLP layers (8 rows x 64 cols tiles, 8-way split-K inside the block)
    mlp_layer<HDIM,  H1DIM,  true,  1><<<dim3(H1DIM  / 64, ROWS / 8), 512>>>(W1, b1, nullptr);
    mlp_layer<H1DIM, H2DIM,  true,  2><<<dim3(H2DIM  / 64, ROWS / 8), 512>>>(W2, b2, nullptr);
    mlp_layer<H2DIM, OUT_DIM, false, 3><<<dim3(OUT_DIM / 64, ROWS / 8), 512>>>(W3, b3, out + OFF_OBJ);

    // similarity masks (bulk of the DRAM traffic)
    sim_fill<<<dim3((DIM64 + 31) / 32, BATCH), 256>>>(out + OFF_S64, HW64, DIM64);
    sim_fill<<<dim3((DIM32 + 31) / 32, BATCH), 256>>>(out + OFF_S32, HW32, DIM32);
}

// round 4
// speedup vs baseline: 2.1231x; 1.1957x over previous
#include <cuda_runtime.h>
#include <math.h>
#include <stdint.h>

// ---------------------------------------------------------------------------
// Problem constants
// ---------------------------------------------------------------------------
#define BATCH   4
#define NBOX    30
#define IN_DIM  768
#define POS_DIM 64
#define HDIM    832
#define H1DIM   512
#define H2DIM   512
#define OUT_DIM 768
#define ROWS    120
#define NRG     15              // row groups of 8

#define HW64  4096
#define DIM64 4126
#define HW32  1024
#define DIM32 1054

#define OFF_OBJ  ((size_t)0)
#define OFF_S64  ((size_t)ROWS * OUT_DIM)
#define OFF_S32  (OFF_S64 + (size_t)BATCH * DIM64 * DIM64)

// Block-role layout (MLP first: all resident in wave 1, chain starts at t=0;
// producers always have lower bids than consumers; sim blocks are independent
// fillers that guarantee forward progress / slot recycling).
#define NB_L1   120             // 15 rg x 8 col-tiles
#define NB_L2   120
#define NB_L3   180             // 15 rg x 12 col-tiles
#define NB_MLP  (NB_L1 + NB_L2 + NB_L3)          // 420
#define RB64    ((DIM64 + 31) / 32)              // 129
#define RB32    ((DIM32 + 31) / 32)              // 33
#define NB_S64  (RB64 * BATCH)                   // 516
#define NB_S32  (RB32 * BATCH)                   // 132
#define GRID    (NB_MLP + NB_S64 + NB_S32)       // 1068

#define SMEM_BYTES (8 * HDIM * 4)                // 26624 B: max(A-tile, bits, sRed)

// ---------------------------------------------------------------------------
// Scratch
// ---------------------------------------------------------------------------
__device__ float g_a1[ROWS * H1DIM];
__device__ float g_a2[ROWS * H2DIM];
__device__ int   g_c1[NRG];
__device__ int   g_c2[NRG];

__global__ void init_counters()
{
    int t = threadIdx.x;
    if (t < NRG) { g_c1[t] = 0; g_c2[t] = 0; }
}

// ---------------------------------------------------------------------------
// Flag protocol
// ---------------------------------------------------------------------------
__device__ __forceinline__ void wait_cnt(int* c, int rg, int target)
{
    if (threadIdx.x == 0) {
        while (atomicAdd(&c[rg], 0) < target) __nanosleep(128);
        __threadfence();
    }
    __syncthreads();
}

__device__ __forceinline__ void signal_cnt(int* c, int rg)
{
    __syncthreads();
    if (threadIdx.x == 0) { __threadfence(); atomicAdd(&c[rg], 1); }
}

// ---------------------------------------------------------------------------
// Stage A-tile helpers (into smem)
// ---------------------------------------------------------------------------
__device__ void stage_h(int rg, const float* __restrict__ boxes,
                        const float* __restrict__ masks,
                        const float* __restrict__ pembed,
                        const float* __restrict__ pos_table,
                        const float* __restrict__ null_pos,
                        const float* __restrict__ null_xyxy,
                        char* s_raw)
{
    float* sAf = (float*)s_raw;
    int t = threadIdx.x;
    for (int idx = t; idx < 8 * HDIM; idx += 256) {
        int r = idx / HDIM, k = idx - r * HDIM;
        int row = rg * 8 + r;
        int n = row % NBOX;
        float m  = masks[row];
        float om = 1.0f - m;
        float v;
        if (k < IN_DIM) {
            v = (pembed[(size_t)row * IN_DIM + k] + pos_table[(size_t)n * IN_DIM + k]) * m
                + om * null_pos[k];
        } else {
            int kk = k - IN_DIM;
            int fi = kk >> 3, c8 = kk & 7, coord = c8 & 3;
            float freq = powf(100.0f, (float)fi * 0.125f);
            float arg  = boxes[(size_t)row * 4 + coord] * freq;
            float e    = (c8 < 4) ? sinf(arg) : cosf(arg);
            v = e * m + om * null_xyxy[kk];
        }
        sAf[r * HDIM + k] = v;
    }
    __syncthreads();
}

template<int K>
__device__ void stage_A(const float* __restrict__ A, int rg, char* s_raw)
{
    float* sAf = (float*)s_raw;
    int t = threadIdx.x;
    for (int idx = t; idx < 8 * K; idx += 256) {
        int r = idx / K, k = idx - r * K;
        sAf[r * K + k] = __ldcg(&A[(size_t)(rg * 8 + r) * K + k]);   // bypass L1
    }
    __syncthreads();
}

// ---------------------------------------------------------------------------
// MLP compute: 8 rows x 64 cols per block, 256 thr = 64 cols x 4 K-slices,
// double-buffered W prefetch, smem split-K reduction (reuses A-tile storage).
// ---------------------------------------------------------------------------
template<int K, int NOUT, bool SILU>
__device__ void mlp_compute(const float* __restrict__ W, const float* __restrict__ bias,
                            float* __restrict__ dst, int rg, int cb, char* s_raw)
{
    constexpr int L  = K / 4;
    constexpr int L4 = L / 4;
    const float4* sA = (const float4*)s_raw;     // [8][K/4]

    int t  = threadIdx.x;
    int j  = t & 63;
    int ks = t >> 6;
    int colBase = cb * 64;

    float acc[8];
#pragma unroll
    for (int r = 0; r < 8; r++) acc[r] = 0.f;

    const float* Wp = W + (size_t)(ks * L) * NOUT + colBase + j;
    const int a4base = ks * L4;

    float w0 = __ldg(Wp + (size_t)0 * NOUT);
    float w1 = __ldg(Wp + (size_t)1 * NOUT);
    float w2 = __ldg(Wp + (size_t)2 * NOUT);
    float w3 = __ldg(Wp + (size_t)3 * NOUT);

#pragma unroll 4
    for (int i4 = 0; i4 < L4; i4++) {
        float n0, n1, n2, n3;
        if (i4 + 1 < L4) {
            const float* Wn = Wp + (size_t)((i4 + 1) * 4) * NOUT;
            n0 = __ldg(Wn + (size_t)0 * NOUT);
            n1 = __ldg(Wn + (size_t)1 * NOUT);
            n2 = __ldg(Wn + (size_t)2 * NOUT);
            n3 = __ldg(Wn + (size_t)3 * NOUT);
        }
#pragma unroll
        for (int r = 0; r < 8; r++) {
            float4 a = sA[r * (K / 4) + a4base + i4];
            acc[r] = fmaf(w0, a.x, acc[r]);
            acc[r] = fmaf(w1, a.y, acc[r]);
            acc[r] = fmaf(w2, a.z, acc[r]);
            acc[r] = fmaf(w3, a.w, acc[r]);
        }
        if (i4 + 1 < L4) { w0 = n0; w1 = n1; w2 = n2; w3 = n3; }
    }

    __syncthreads();                             // done reading sA
    float* sRed = (float*)s_raw;                 // [4][8][65] (reuses A storage)
#pragma unroll
    for (int r = 0; r < 8; r++) sRed[(ks * 8 + r) * 65 + j] = acc[r];
    __syncthreads();

    float bj = bias[colBase + j];
#pragma unroll
    for (int rr = 0; rr < 2; rr++) {
        int r = ks * 2 + rr;
        float v = bj;
#pragma unroll
        for (int s = 0; s < 4; s++) v += sRed[(s * 8 + r) * 65 + j];
        if (SILU) v = v / (1.0f + expf(-v));
        dst[(size_t)(rg * 8 + r) * NOUT + colBase + j] = v;
    }
}

// ---------------------------------------------------------------------------
// Sim block: self-contained. Computes the bits table for its batch into smem
// (cheap vs its DRAM writes), then streams 32 rows of the sim matrix.
// ---------------------------------------------------------------------------
template<int SIZE>
__device__ void sim_block(float* __restrict__ outBase, int b, int rowblk,
                          const float* __restrict__ boxes,
                          const float* __restrict__ masks,
                          char* s_raw, int (*s_box)[NBOX], unsigned* s_valid)
{
    constexpr int HW  = SIZE * SIZE;
    constexpr int DIM = HW + NBOX;
    unsigned* sbits = (unsigned*)s_raw;
    int t = threadIdx.x;

    if (t == 0) *s_valid = 0u;
    __syncthreads();
    if (t < NBOX) {
        const float* bb = boxes + ((size_t)b * NBOX + t) * 4;
        s_box[0][t] = (int)rintf(bb[0] * (float)SIZE);
        s_box[1][t] = (int)rintf(bb[1] * (float)SIZE);
        s_box[2][t] = (int)rintf(bb[2] * (float)SIZE);
        s_box[3][t] = (int)rintf(bb[3] * (float)SIZE);
        if (t < NBOX - 1 && masks[b * NBOX + t] == 1.0f)
            atomicOr(s_valid, 1u << t);
    }
    __syncthreads();
    unsigned vm = *s_valid;

    for (int p = t; p < HW; p += 256) {
        int y = p / SIZE, x = p - y * SIZE;
        unsigned m = 0u;
#pragma unroll
        for (int n = 0; n < NBOX - 1; n++) {
            bool in = (y >= s_box[1][n]) & (y < s_box[3][n]) &
                      (x >= s_box[0][n]) & (x < s_box[2][n]);
            if (in) m |= (1u << n);
        }
        m &= vm;
        if (m == 0u) m = (1u << (NBOX - 1));
        sbits[p] = m;
    }
    __syncthreads();

    const uint2* sb2 = (const uint2*)sbits;
    constexpr int half = DIM >> 1;
    constexpr int HW2  = HW >> 1;
    size_t bbase = (size_t)b * DIM * DIM;

    for (int pi = 0; pi < 32; pi++) {
        int p = rowblk * 32 + pi;
        if (p >= DIM) break;
        float2* rowp = (float2*)(outBase + bbase + (size_t)p * DIM);
        if (p >= HW) {
            float2 z = make_float2(0.f, 0.f);
            for (int i = t; i < half; i += 256) rowp[i] = z;
        } else {
            unsigned rb = sbits[p];
            for (int i = t; i < half; i += 256) {
                float2 v;
                if (i < HW2) {
                    uint2 s = sb2[i];
                    v.x = (rb & s.x) ? 1.f : 0.f;
                    v.y = (rb & s.y) ? 1.f : 0.f;
                } else {
                    int n = i * 2 - HW;
                    v.x = ((rb >> n)       & 1u) ? 1.f : 0.f;
                    v.y = ((rb >> (n + 1)) & 1u) ? 1.f : 0.f;
                }
                rowp[i] = v;
            }
        }
    }
}

// ---------------------------------------------------------------------------
// Mega kernel: block-specialized fusion of everything.
// ---------------------------------------------------------------------------
__global__ void __launch_bounds__(256)
mega_kernel(const float* __restrict__ boxes, const float* __restrict__ masks,
            const float* __restrict__ pembed, const float* __restrict__ pos_table,
            const float* __restrict__ W1, const float* __restrict__ b1,
            const float* __restrict__ W2, const float* __restrict__ b2,
            const float* __restrict__ W3, const float* __restrict__ b3,
            const float* __restrict__ null_pos, const float* __restrict__ null_xyxy,
            float* __restrict__ out)
{
    __shared__ __align__(16) char s_raw[SMEM_BYTES];
    __shared__ int      s_box[4][NBOX];
    __shared__ unsigned s_valid;

    int bid = blockIdx.x;

    if (bid < NB_L1) {
        int rg = bid >> 3, cb = bid & 7;
        stage_h(rg, boxes, masks, pembed, pos_table, null_pos, null_xyxy, s_raw);
        mlp_compute<HDIM, H1DIM, true>(W1, b1, g_a1, rg, cb, s_raw);
        signal_cnt(g_c1, rg);
    } else if (bid < NB_L1 + NB_L2) {
        int i = bid - NB_L1;
        int rg = i >> 3, cb = i & 7;
        wait_cnt(g_c1, rg, 8);
        stage_A<H1DIM>(g_a1, rg, s_raw);
        mlp_compute<H1DIM, H2DIM, true>(W2, b2, g_a2, rg, cb, s_raw);
        signal_cnt(g_c2, rg);
    } else if (bid < NB_MLP) {
        int i = bid - (NB_L1 + NB_L2);
        int rg = i / 12, cb = i - rg * 12;
        wait_cnt(g_c2, rg, 8);
        stage_A<H2DIM>(g_a2, rg, s_raw);
        mlp_compute<H2DIM, OUT_DIM, false>(W3, b3, out + OFF_OBJ, rg, cb, s_raw);
    } else if (bid < NB_MLP + NB_S64) {
        int i = bid - NB_MLP;
        int b = i / RB64, rb = i - b * RB64;
        sim_block<64>(out + OFF_S64, b, rb, boxes, masks, s_raw, s_box, &s_valid);
    } else {
        int i = bid - (NB_MLP + NB_S64);
        int b = i / RB32, rb = i - b * RB32;
        sim_block<32>(out + OFF_S32, b, rb, boxes, masks, s_raw, s_box, &s_valid);
    }
}

// ---------------------------------------------------------------------------
// Launch
// ---------------------------------------------------------------------------
extern "C" void kernel_launch(void* const* d_in, const int* in_sizes, int n_in,
                              void* d_out, int out_size)
{
    const float* boxes      = (const float*)d_in[0];
    const float* masks      = (const float*)d_in[1];
    const float* pembed     = (const float*)d_in[2];
    const float* pos_table  = (const float*)d_in[3];
    const float* W1         = (const float*)d_in[4];
    const float* b1         = (const float*)d_in[5];
    const float* W2         = (const float*)d_in[6];
    const float* b2         = (const float*)d_in[7];
    const float* W3         = (const float*)d_in[8];
    const float* b3         = (const float*)d_in[9];
    const float* null_pos   = (const float*)d_in[10];
    const float* null_xyxy  = (const float*)d_in[11];
    float* out = (float*)d_out;

    init_counters<<<1, 32>>>();
    mega_kernel<<<GRID, 256>>>(boxes, masks, pembed, pos_table,
                               W1, b1, W2, b2, W3, b3,
                               null_pos, null_xyxy, out);
}

// round 5
// speedup vs baseline: 2.7068x; 1.2749x over previous
#include <cuda_runtime.h>
#include <math.h>
#include <stdint.h>

// ---------------------------------------------------------------------------
// Problem constants
// ---------------------------------------------------------------------------
#define BATCH   4
#define NBOX    30
#define IN_DIM  768
#define POS_DIM 64
#define HDIM    832
#define H1DIM   512
#define H2DIM   512
#define OUT_DIM 768
#define ROWS    120
#define NRG     15              // row groups of 8

#define HW64  4096
#define DIM64 4126
#define HW32  1024
#define DIM32 1054

#define OFF_OBJ  ((size_t)0)
#define OFF_S64  ((size_t)ROWS * OUT_DIM)
#define OFF_S32  (OFF_S64 + (size_t)BATCH * DIM64 * DIM64)

// Block-role layout. Producers (bits, MLP layers) get the lowest bids so they
// are resident in wave 1; sim blocks are independent consumers/fillers.
#define NB_B64   32             // 8 per batch
#define NB_B32   4              // 1 per batch
#define NB_BITS  (NB_B64 + NB_B32)               // 36
#define NB_L1    120            // 15 rg x 8 col-tiles
#define NB_L2    120
#define NB_L3    180            // 15 rg x 12 col-tiles
#define NB_MLP   (NB_L1 + NB_L2 + NB_L3)         // 420
#define RB64     ((DIM64 + 31) / 32)             // 129
#define RB32     ((DIM32 + 31) / 32)             // 33
#define NB_S64   (RB64 * BATCH)                  // 516
#define NB_S32   (RB32 * BATCH)                  // 132
#define GRID     (NB_BITS + NB_MLP + NB_S64 + NB_S32)   // 1104

#define SMEM_BYTES (8 * HDIM * 4)                // 26624 B: max(A-tile, bits, sRed)

// ---------------------------------------------------------------------------
// Scratch
// ---------------------------------------------------------------------------
__device__ float    g_a1[ROWS * H1DIM];
__device__ float    g_a2[ROWS * H2DIM];
__device__ unsigned g_bits64[BATCH * HW64];
__device__ unsigned g_bits32[BATCH * HW32];
__device__ int      g_c1[NRG];
__device__ int      g_c2[NRG];
__device__ int      g_cb64[BATCH];
__device__ int      g_cb32[BATCH];

__global__ void init_counters()
{
    int t = threadIdx.x;
    if (t < NRG)   { g_c1[t] = 0; g_c2[t] = 0; }
    if (t < BATCH) { g_cb64[t] = 0; g_cb32[t] = 0; }
}

// ---------------------------------------------------------------------------
// Flag protocol (gpu-scope)
// ---------------------------------------------------------------------------
__device__ __forceinline__ void wait_cnt(int* c, int idx, int target)
{
    if (threadIdx.x == 0) {
        while (atomicAdd(&c[idx], 0) < target) __nanosleep(128);
        __threadfence();
    }
    __syncthreads();
}

__device__ __forceinline__ void signal_cnt(int* c, int idx)
{
    __syncthreads();
    if (threadIdx.x == 0) { __threadfence(); atomicAdd(&c[idx], 1); }
}

// ---------------------------------------------------------------------------
// Bits producer: rasterize one slice of one batch's membership masks.
// ---------------------------------------------------------------------------
template<int SIZE>
__device__ void bits_block(int b, int slice, int nslices,
                           const float* __restrict__ boxes,
                           const float* __restrict__ masks,
                           unsigned* __restrict__ gbits, int* flag,
                           int (*s_box)[NBOX], unsigned* s_valid)
{
    constexpr int HW = SIZE * SIZE;
    int t = threadIdx.x;
    if (t == 0) *s_valid = 0u;
    __syncthreads();
    if (t < NBOX) {
        const float* bb = boxes + ((size_t)b * NBOX + t) * 4;
        // boxes*SIZE exact (power-of-2 scale); rintf = round-half-even = jnp.round
        s_box[0][t] = (int)rintf(bb[0] * (float)SIZE);
        s_box[1][t] = (int)rintf(bb[1] * (float)SIZE);
        s_box[2][t] = (int)rintf(bb[2] * (float)SIZE);
        s_box[3][t] = (int)rintf(bb[3] * (float)SIZE);
        if (t < NBOX - 1 && masks[b * NBOX + t] == 1.0f)
            atomicOr(s_valid, 1u << t);
    }
    __syncthreads();
    unsigned vm = *s_valid;

    int chunk = HW / nslices;
    int p0 = slice * chunk;
    for (int p = p0 + t; p < p0 + chunk; p += 256) {
        int y = p / SIZE, x = p - y * SIZE;
        unsigned m = 0u;
#pragma unroll
        for (int n = 0; n < NBOX - 1; n++) {
            bool in = (y >= s_box[1][n]) & (y < s_box[3][n]) &
                      (x >= s_box[0][n]) & (x < s_box[2][n]);
            if (in) m |= (1u << n);
        }
        m &= vm;
        if (m == 0u) m = (1u << (NBOX - 1));
        gbits[(size_t)b * HW + p] = m;
    }
    signal_cnt(flag, b);
}

// ---------------------------------------------------------------------------
// MLP helpers
// ---------------------------------------------------------------------------
__device__ void stage_h(int rg, const float* __restrict__ boxes,
                        const float* __restrict__ masks,
                        const float* __restrict__ pembed,
                        const float* __restrict__ pos_table,
                        const float* __restrict__ null_pos,
                        const float* __restrict__ null_xyxy,
                        char* s_raw)
{
    float* sAf = (float*)s_raw;
    int t = threadIdx.x;
    for (int idx = t; idx < 8 * HDIM; idx += 256) {
        int r = idx / HDIM, k = idx - r * HDIM;
        int row = rg * 8 + r;
        int n = row % NBOX;
        float m  = masks[row];
        float om = 1.0f - m;
        float v;
        if (k < IN_DIM) {
            v = (pembed[(size_t)row * IN_DIM + k] + pos_table[(size_t)n * IN_DIM + k]) * m
                + om * null_pos[k];
        } else {
            int kk = k - IN_DIM;
            int fi = kk >> 3, c8 = kk & 7, coord = c8 & 3;
            float freq = powf(100.0f, (float)fi * 0.125f);
            float arg  = boxes[(size_t)row * 4 + coord] * freq;
            float e    = (c8 < 4) ? sinf(arg) : cosf(arg);
            v = e * m + om * null_xyxy[kk];
        }
        sAf[r * HDIM + k] = v;
    }
    __syncthreads();
}

template<int K>
__device__ void stage_A(const float* __restrict__ A, int rg, char* s_raw)
{
    float* sAf = (float*)s_raw;
    int t = threadIdx.x;
    for (int idx = t; idx < 8 * K; idx += 256) {
        int r = idx / K, k = idx - r * K;
        sAf[r * K + k] = __ldcg(&A[(size_t)(rg * 8 + r) * K + k]);   // bypass L1
    }
    __syncthreads();
}

template<int K, int NOUT, bool SILU>
__device__ void mlp_compute(const float* __restrict__ W, const float* __restrict__ bias,
                            float* __restrict__ dst, int rg, int cb, char* s_raw)
{
    constexpr int L  = K / 4;
    constexpr int L4 = L / 4;
    const float4* sA = (const float4*)s_raw;     // [8][K/4]

    int t  = threadIdx.x;
    int j  = t & 63;
    int ks = t >> 6;
    int colBase = cb * 64;

    float acc[8];
#pragma unroll
    for (int r = 0; r < 8; r++) acc[r] = 0.f;

    const float* Wp = W + (size_t)(ks * L) * NOUT + colBase + j;
    const int a4base = ks * L4;

    float w0 = __ldg(Wp + (size_t)0 * NOUT);
    float w1 = __ldg(Wp + (size_t)1 * NOUT);
    float w2 = __ldg(Wp + (size_t)2 * NOUT);
    float w3 = __ldg(Wp + (size_t)3 * NOUT);

#pragma unroll 4
    for (int i4 = 0; i4 < L4; i4++) {
        float n0, n1, n2, n3;
        if (i4 + 1 < L4) {
            const float* Wn = Wp + (size_t)((i4 + 1) * 4) * NOUT;
            n0 = __ldg(Wn + (size_t)0 * NOUT);
            n1 = __ldg(Wn + (size_t)1 * NOUT);
            n2 = __ldg(Wn + (size_t)2 * NOUT);
            n3 = __ldg(Wn + (size_t)3 * NOUT);
        }
#pragma unroll
        for (int r = 0; r < 8; r++) {
            float4 a = sA[r * (K / 4) + a4base + i4];
            acc[r] = fmaf(w0, a.x, acc[r]);
            acc[r] = fmaf(w1, a.y, acc[r]);
            acc[r] = fmaf(w2, a.z, acc[r]);
            acc[r] = fmaf(w3, a.w, acc[r]);
        }
        if (i4 + 1 < L4) { w0 = n0; w1 = n1; w2 = n2; w3 = n3; }
    }

    __syncthreads();                             // done reading sA
    float* sRed = (float*)s_raw;                 // [4][8][65] (reuses A storage)
#pragma unroll
    for (int r = 0; r < 8; r++) sRed[(ks * 8 + r) * 65 + j] = acc[r];
    __syncthreads();

    float bj = bias[colBase + j];
#pragma unroll
    for (int rr = 0; rr < 2; rr++) {
        int r = ks * 2 + rr;
        float v = bj;
#pragma unroll
        for (int s = 0; s < 4; s++) v += sRed[(s * 8 + r) * 65 + j];
        if (SILU) v = v / (1.0f + expf(-v));
        dst[(size_t)(rg * 8 + r) * NOUT + colBase + j] = v;
    }
}

// ---------------------------------------------------------------------------
// Sim consumer: wait for batch bits, stage to smem, stream 32 rows with
// float4 streaming stores. Requires DIM % 4 == 2, HW % 4 == 0.
// ---------------------------------------------------------------------------
template<int SIZE>
__device__ void sim_block(float* __restrict__ outBase, int b, int rowblk,
                          const unsigned* __restrict__ gbits,
                          int* flag, int target, char* s_raw)
{
    constexpr int HW  = SIZE * SIZE;
    constexpr int DIM = HW + NBOX;
    constexpr int N4  = (DIM - 2) / 4;
    unsigned* sbits = (unsigned*)s_raw;
    int t = threadIdx.x;

    wait_cnt(flag, b, target);

    {   // stage bits (16 KB max) via uint4 .cg loads
        const uint4* g4 = (const uint4*)(gbits + (size_t)b * HW);
        uint4* s4 = (uint4*)sbits;
        for (int i = t; i < HW / 4; i += 256) s4[i] = __ldcg(&g4[i]);
    }
    __syncthreads();

    const uint2* sb2 = (const uint2*)sbits;
    size_t bbase = (size_t)b * DIM * DIM;

    for (int pi = 0; pi < 32; pi++) {
        int p = rowblk * 32 + pi;
        if (p >= DIM) break;
        float* rowp = outBase + bbase + (size_t)p * DIM;
        int head = (p & 1) ? 2 : 0;          // DIM % 4 == 2 -> odd rows offset by 2
        float4* out4 = (float4*)(rowp + head);   // 16B aligned

        if (p >= HW) {                       // zero rows
            float4 z4 = make_float4(0.f, 0.f, 0.f, 0.f);
            for (int i = t; i < N4; i += 256) __stcs(&out4[i], z4);
            if (t == 0) {
                if (head) { rowp[0] = 0.f; rowp[1] = 0.f; }
                else      { rowp[DIM - 2] = 0.f; rowp[DIM - 1] = 0.f; }
            }
            continue;
        }

        unsigned rb = sbits[p];
        if (t == 0) {
            if (head) {                      // cols 0,1 (< HW)
                rowp[0] = (rb & sbits[0]) ? 1.f : 0.f;
                rowp[1] = (rb & sbits[1]) ? 1.f : 0.f;
            } else {                         // cols HW+28, HW+29
                rowp[DIM - 2] = ((rb >> (NBOX - 2)) & 1u) ? 1.f : 0.f;
                rowp[DIM - 1] = ((rb >> (NBOX - 1)) & 1u) ? 1.f : 0.f;
            }
        }
        for (int i = t; i < N4; i += 256) {
            int c0 = head + 4 * i;           // even
            float4 v;
            if (c0 + 3 < HW) {
                uint2 e0 = sb2[c0 >> 1];
                uint2 e1 = sb2[(c0 >> 1) + 1];
                v.x = (rb & e0.x) ? 1.f : 0.f;
                v.y = (rb & e0.y) ? 1.f : 0.f;
                v.z = (rb & e1.x) ? 1.f : 0.f;
                v.w = (rb & e1.y) ? 1.f : 0.f;
            } else if (c0 >= HW) {
                int n = c0 - HW;
                v.x = ((rb >> n)       & 1u) ? 1.f : 0.f;
                v.y = ((rb >> (n + 1)) & 1u) ? 1.f : 0.f;
                v.z = ((rb >> (n + 2)) & 1u) ? 1.f : 0.f;
                v.w = ((rb >> (n + 3)) & 1u) ? 1.f : 0.f;
            } else {                         // single straddling float4 (odd rows)
                float tmp[4];
#pragma unroll
                for (int k = 0; k < 4; k++) {
                    int q = c0 + k;
                    tmp[k] = (q < HW) ? ((rb & sbits[q]) ? 1.f : 0.f)
                                      : (((rb >> (q - HW)) & 1u) ? 1.f : 0.f);
                }
                v = make_float4(tmp[0], tmp[1], tmp[2], tmp[3]);
            }
            __stcs(&out4[i], v);
        }
    }
}

// ---------------------------------------------------------------------------
// Mega kernel
// ---------------------------------------------------------------------------
__global__ void __launch_bounds__(256, 3)
mega_kernel(const float* __restrict__ boxes, const float* __restrict__ masks,
            const float* __restrict__ pembed, const float* __restrict__ pos_table,
            const float* __restrict__ W1, const float* __restrict__ b1,
            const float* __restrict__ W2, const float* __restrict__ b2,
            const float* __restrict__ W3, const float* __restrict__ b3,
            const float* __restrict__ null_pos, const float* __restrict__ null_xyxy,
            float* __restrict__ out)
{
    __shared__ __align__(16) char s_raw[SMEM_BYTES];
    __shared__ int      s_box[4][NBOX];
    __shared__ unsigned s_valid;

    int bid = blockIdx.x;

    if (bid < NB_B64) {
        int b = bid >> 3, slice = bid & 7;
        bits_block<64>(b, slice, 8, boxes, masks, g_bits64, g_cb64, s_box, &s_valid);
    } else if (bid < NB_BITS) {
        int b = bid - NB_B64;
        bits_block<32>(b, 0, 1, boxes, masks, g_bits32, g_cb32, s_box, &s_valid);
    } else if (bid < NB_BITS + NB_L1) {
        int i = bid - NB_BITS;
        int rg = i >> 3, cb = i & 7;
        stage_h(rg, boxes, masks, pembed, pos_table, null_pos, null_xyxy, s_raw);
        mlp_compute<HDIM, H1DIM, true>(W1, b1, g_a1, rg, cb, s_raw);
        signal_cnt(g_c1, rg);
    } else if (bid < NB_BITS + NB_L1 + NB_L2) {
        int i = bid - (NB_BITS + NB_L1);
        int rg = i >> 3, cb = i & 7;
        wait_cnt(g_c1, rg, 8);
        stage_A<H1DIM>(g_a1, rg, s_raw);
        mlp_compute<H1DIM, H2DIM, true>(W2, b2, g_a2, rg, cb, s_raw);
        signal_cnt(g_c2, rg);
    } else if (bid < NB_BITS + NB_MLP) {
        int i = bid - (NB_BITS + NB_L1 + NB_L2);
        int rg = i / 12, cb = i - rg * 12;
        wait_cnt(g_c2, rg, 8);
        stage_A<H2DIM>(g_a2, rg, s_raw);
        mlp_compute<H2DIM, OUT_DIM, false>(W3, b3, out + OFF_OBJ, rg, cb, s_raw);
    } else if (bid < NB_BITS + NB_MLP + NB_S64) {
        int i = bid - (NB_BITS + NB_MLP);
        int b = i / RB64, rb = i - b * RB64;
        sim_block<64>(out + OFF_S64, b, rb, g_bits64, g_cb64, 8, s_raw);
    } else {
        int i = bid - (NB_BITS + NB_MLP + NB_S64);
        int b = i / RB32, rb = i - b * RB32;
        sim_block<32>(out + OFF_S32, b, rb, g_bits32, g_cb32, 1, s_raw);
    }
}

// ---------------------------------------------------------------------------
// Launch
// ---------------------------------------------------------------------------
extern "C" void kernel_launch(void* const* d_in, const int* in_sizes, int n_in,
                              void* d_out, int out_size)
{
    const float* boxes      = (const float*)d_in[0];
    const float* masks      = (const float*)d_in[1];
    const float* pembed     = (const float*)d_in[2];
    const float* pos_table  = (const float*)d_in[3];
    const float* W1         = (const float*)d_in[4];
    const float* b1         = (const float*)d_in[5];
    const float* W2         = (const float*)d_in[6];
    const float* b2         = (const float*)d_in[7];
    const float* W3         = (const float*)d_in[8];
    const float* b3         = (const float*)d_in[9];
    const float* null_pos   = (const float*)d_in[10];
    const float* null_xyxy  = (const float*)d_in[11];
    float* out = (float*)d_out;

    init_counters<<<1, 32>>>();
    mega_kernel<<<GRID, 256>>>(boxes, masks, pembed, pos_table,
                               W1, b1, W2, b2, W3, b3,
                               null_pos, null_xyxy, out);
}